// round 1
// baseline (speedup 1.0000x reference)
#include <cuda_runtime.h>
#include <cuda_bf16.h>

// Problem shape (fixed by dataset)
#define MM 2048
#define NN 4096
#define KK 4096
#define GROUPS 32      // KK / 128
#define KP (KK / 8)    // packed rows of qweight

// 64 MB fp32 scratch for dequantized weights (allocation-free rule: __device__ global)
__device__ float g_wdeq[(size_t)KK * NN];

// ---------------------------------------------------------------------------
// Kernel 1: dequantize 4-bit packed weights -> fp32 [KK, NN]
// qweight: [KK/8, NN] int32, 8 nibbles along K per int32.
// deq[k][n] = (float(nibble) - clip(round(zp[g][n]),0,15)) * clip(s[g][n],1e-5,1e4)
// ---------------------------------------------------------------------------
__global__ void dequant_kernel(const int* __restrict__ qw,
                               const float* __restrict__ scales,
                               const float* __restrict__ zp)
{
    int idx = blockIdx.x * blockDim.x + threadIdx.x;
    if (idx >= KP * NN) return;
    int n  = idx & (NN - 1);
    int kp = idx >> 12;            // idx / NN  (NN = 4096 = 2^12)
    int g  = kp >> 4;              // (kp*8)/128

    float s = fminf(fmaxf(scales[g * NN + n], 1e-5f), 1e4f);
    float z = fminf(fmaxf(rintf(zp[g * NN + n]), 0.0f), 15.0f);
    int   q = qw[idx];

    #pragma unroll
    for (int j = 0; j < 8; ++j) {
        int w = (q >> (4 * j)) & 15;
        g_wdeq[(size_t)(kp * 8 + j) * NN + n] = ((float)w - z) * s;
    }
}

// ---------------------------------------------------------------------------
// Kernel 2: SGEMM  C[M,N] = A[M,K] * g_wdeq[K,N] + bias
// 128x128 block tile, BK=16, 256 threads, 8x8 per-thread microtile.
// ---------------------------------------------------------------------------
#define BM 128
#define BN 128
#define BK 16
#define PAD 4   // As row pad: makes transposed stores conflict-free-ish

__global__ __launch_bounds__(256, 2)
void sgemm_kernel(const float* __restrict__ A,
                  const float* __restrict__ bias,
                  float* __restrict__ C)
{
    __shared__ float As[BK][BM + PAD];   // [k][m]
    __shared__ float Bs[BK][BN];         // [k][n]

    const int tid = threadIdx.x;
    const int bx  = blockIdx.x;   // N tile
    const int by  = blockIdx.y;   // M tile

    // A tile loads: 128 rows x 16 cols = 512 float4; thread t loads rows t/4 and t/4+64
    const int arow = tid >> 2;
    const int acol = (tid & 3) * 4;
    // B tile loads: 16 rows x 128 cols = 512 float4; thread t loads rows t/32 and t/32+8
    const int brow = tid >> 5;
    const int bcol = (tid & 31) * 4;

    const float* Ablk = A + (size_t)(by * BM) * KK;
    const float* Bblk = g_wdeq + bx * BN;

    // compute mapping: 16x16 thread grid, each 8x8 outputs
    const int ty = tid >> 4;     // 0..15 (M)
    const int tx = tid & 15;     // 0..15 (N)

    float acc[8][8];
    #pragma unroll
    for (int i = 0; i < 8; ++i)
        #pragma unroll
        for (int j = 0; j < 8; ++j) acc[i][j] = 0.0f;

    for (int k0 = 0; k0 < KK; k0 += BK) {
        // load A tile (transposed into As[k][m])
        #pragma unroll
        for (int r = 0; r < 2; ++r) {
            int m = arow + r * 64;
            float4 v = *(const float4*)(Ablk + (size_t)m * KK + k0 + acol);
            As[acol + 0][m] = v.x;
            As[acol + 1][m] = v.y;
            As[acol + 2][m] = v.z;
            As[acol + 3][m] = v.w;
        }
        // load B tile
        #pragma unroll
        for (int r = 0; r < 2; ++r) {
            int k = brow + r * 8;
            float4 v = *(const float4*)(Bblk + (size_t)(k0 + k) * NN + bcol);
            *(float4*)&Bs[k][bcol] = v;
        }
        __syncthreads();

        #pragma unroll
        for (int kk = 0; kk < BK; ++kk) {
            float ra[8], rb[8];
            #pragma unroll
            for (int i = 0; i < 2; ++i) {
                float4 v = *(const float4*)&As[kk][ty * 8 + i * 4];
                ra[i*4+0] = v.x; ra[i*4+1] = v.y; ra[i*4+2] = v.z; ra[i*4+3] = v.w;
            }
            #pragma unroll
            for (int j = 0; j < 2; ++j) {
                float4 v = *(const float4*)&Bs[kk][tx * 8 + j * 4];
                rb[j*4+0] = v.x; rb[j*4+1] = v.y; rb[j*4+2] = v.z; rb[j*4+3] = v.w;
            }
            #pragma unroll
            for (int i = 0; i < 8; ++i)
                #pragma unroll
                for (int j = 0; j < 8; ++j)
                    acc[i][j] = fmaf(ra[i], rb[j], acc[i][j]);
        }
        __syncthreads();
    }

    // epilogue: add bias, write out (float4)
    const int crow0 = by * BM + ty * 8;
    const int ccol0 = bx * BN + tx * 8;
    #pragma unroll
    for (int i = 0; i < 8; ++i) {
        float* crow = C + (size_t)(crow0 + i) * NN + ccol0;
        #pragma unroll
        for (int j4 = 0; j4 < 2; ++j4) {
            float4 b = *(const float4*)(bias + ccol0 + j4 * 4);
            float4 o;
            o.x = acc[i][j4*4+0] + b.x;
            o.y = acc[i][j4*4+1] + b.y;
            o.z = acc[i][j4*4+2] + b.z;
            o.w = acc[i][j4*4+3] + b.w;
            *(float4*)(crow + j4 * 4) = o;
        }
    }
}

// ---------------------------------------------------------------------------
// Launcher. Inputs in metadata order: x, scales, zero_points, bias, qweight
// ---------------------------------------------------------------------------
extern "C" void kernel_launch(void* const* d_in, const int* in_sizes, int n_in,
                              void* d_out, int out_size)
{
    const float* x      = (const float*)d_in[0];
    const float* scales = (const float*)d_in[1];
    const float* zp     = (const float*)d_in[2];
    const float* bias   = (const float*)d_in[3];
    const int*   qw     = (const int*)d_in[4];
    float*       out    = (float*)d_out;

    // 1) dequantize weights into fp32 scratch
    {
        int total = KP * NN;
        int threads = 256;
        int blocks = (total + threads - 1) / threads;
        dequant_kernel<<<blocks, threads>>>(qw, scales, zp);
    }
    // 2) SGEMM + bias
    {
        dim3 grid(NN / BN, MM / BM);
        sgemm_kernel<<<grid, 256>>>(x, bias, out);
    }
}

// round 3
// speedup vs baseline: 3.4095x; 3.4095x over previous
#include <cuda_runtime.h>
#include <cuda_bf16.h>
#include <cstdint>

#define MMV 2048
#define NNV 4096
#define KKV 4096

// Scratch (__device__ globals; no allocations allowed)
__device__ __align__(16) __nv_bfloat16 g_xh[(size_t)MMV * KKV];  // bf16(x)
__device__ __align__(16) __nv_bfloat16 g_xl[(size_t)MMV * KKV];  // bf16(x - bf16(x))
__device__ __align__(16) __nv_bfloat16 g_wi[(size_t)KKV * NNV];  // (q - z) exact integer, [K][N]

// ---------------------------------------------------------------------------
// asm helpers (all plain-sm_103-legal: ldmatrix / mma.sync / cp.async)
// ---------------------------------------------------------------------------
__device__ __forceinline__ void ldsm4(uint32_t* r, uint32_t addr) {
    asm volatile("ldmatrix.sync.aligned.m8n8.x4.shared.b16 {%0,%1,%2,%3}, [%4];"
                 : "=r"(r[0]), "=r"(r[1]), "=r"(r[2]), "=r"(r[3]) : "r"(addr));
}
__device__ __forceinline__ void ldsm4t(uint32_t* r, uint32_t addr) {
    asm volatile("ldmatrix.sync.aligned.m8n8.x4.trans.shared.b16 {%0,%1,%2,%3}, [%4];"
                 : "=r"(r[0]), "=r"(r[1]), "=r"(r[2]), "=r"(r[3]) : "r"(addr));
}
__device__ __forceinline__ void mma_bf16(float* c, const uint32_t* a, const uint32_t* b) {
    asm volatile("mma.sync.aligned.m16n8k16.row.col.f32.bf16.bf16.f32 "
                 "{%0,%1,%2,%3}, {%4,%5,%6,%7}, {%8,%9}, {%0,%1,%2,%3};"
                 : "+f"(c[0]), "+f"(c[1]), "+f"(c[2]), "+f"(c[3])
                 : "r"(a[0]), "r"(a[1]), "r"(a[2]), "r"(a[3]), "r"(b[0]), "r"(b[1]));
}
__device__ __forceinline__ void cpa16(uint32_t s, const void* g) {
    asm volatile("cp.async.cg.shared.global [%0], [%1], 16;" :: "r"(s), "l"(g));
}
#define CP_COMMIT() asm volatile("cp.async.commit_group;" ::: "memory")
#define CP_WAIT3()  asm volatile("cp.async.wait_group 3;" ::: "memory")

// ---------------------------------------------------------------------------
// Prep 1: split x into bf16 hi + bf16 lo residual
// ---------------------------------------------------------------------------
__global__ void split_x_kernel(const float4* __restrict__ x4) {
    size_t i = (size_t)blockIdx.x * blockDim.x + threadIdx.x;  // M*K/4 threads
    float4 v = x4[i];
    float f[4] = {v.x, v.y, v.z, v.w};
    __align__(8) __nv_bfloat16 h[4], l[4];
#pragma unroll
    for (int j = 0; j < 4; ++j) {
        h[j] = __float2bfloat16(f[j]);
        l[j] = __float2bfloat16(f[j] - __bfloat162float(h[j]));
    }
    ((uint2*)g_xh)[i] = *(uint2*)h;
    ((uint2*)g_xl)[i] = *(uint2*)l;
}

// ---------------------------------------------------------------------------
// Prep 2: Wint[k][n] = (q - clip(round(zp),0,15))  (exact small integer)
// ---------------------------------------------------------------------------
__global__ void dequant_w_kernel(const int* __restrict__ qw,
                                 const float* __restrict__ zp) {
    int T = blockIdx.x * blockDim.x + threadIdx.x;  // KKV/8 * NNV threads
    int n  = T & (NNV - 1);
    int kp = T >> 12;
    int g  = kp >> 4;           // GROUP=128 -> 16 packed rows per group
    float z = fminf(fmaxf(rintf(zp[g * NNV + n]), 0.0f), 15.0f);
    int q = qw[(size_t)kp * NNV + n];
#pragma unroll
    for (int j = 0; j < 8; ++j) {
        int w = (q >> (4 * j)) & 15;
        g_wi[(size_t)(kp * 8 + j) * NNV + n] = __float2bfloat16((float)w - z);
    }
}

// ---------------------------------------------------------------------------
// GEMM: C = (xh + xl) @ Wint  with per-group scale fold, + bias
// CTA tile 128x128, BK=32, 8 warps (4m x 2n), warp tile 32x64
// smem: [0,16K) clipped scales for this n-strip; 4 stages x (Ah 8K | Al 8K | B 8K)
// ---------------------------------------------------------------------------
#define NS 4
#define STG_BYTES 24576
#define SM_STAGES 16384
#define SMEM_TOTAL (SM_STAGES + NS * STG_BYTES)   // 114688

__global__ void __launch_bounds__(256, 1)
gemm_kernel(const float* __restrict__ scales,
            const float* __restrict__ bias,
            float* __restrict__ C)
{
    extern __shared__ __align__(16) char smem[];
    const uint32_t sb = (uint32_t)__cvta_generic_to_shared(smem);
    const int tid = threadIdx.x, lane = tid & 31, wid = tid >> 5;
    const int wm = wid & 3, wn = wid >> 2;
    const int m0 = blockIdx.y * 128, n0 = blockIdx.x * 128;

    // stage clipped scales [32 groups][128 cols]
    float* s_sc = (float*)smem;
    for (int i = tid; i < 4096; i += 256) {
        int g = i >> 7, j = i & 127;
        float s = scales[g * NNV + n0 + j];
        s_sc[i] = fminf(fmaxf(s, 1e-5f), 1e4f);
    }

    // per-thread cp.async chunk coords
    // A tiles: 128 rows x 4 chunks(16B); B tile: 32 rows x 16 chunks
    // loader lambda
    auto load_stage = [&](int kt, int st) {
        uint32_t base = sb + SM_STAGES + st * STG_BYTES;
#pragma unroll
        for (int j = 0; j < 2; ++j) {
            int q = tid + j * 256;
            int r = q >> 2, c = q & 3;
            uint32_t so = base + (uint32_t)(r * 4 + (c ^ ((r >> 1) & 3))) * 16;
            size_t go = (size_t)(m0 + r) * KKV + kt * 32 + c * 8;
            cpa16(so,        g_xh + go);
            cpa16(so + 8192, g_xl + go);
        }
#pragma unroll
        for (int j = 0; j < 2; ++j) {
            int q = tid + j * 256;
            int r = q >> 4, c = q & 15;
            uint32_t so = base + 16384 + (uint32_t)(r * 16 + (c ^ (r & 7))) * 16;
            cpa16(so, g_wi + (size_t)(kt * 32 + r) * NNV + n0 + c * 8);
        }
    };

    // fill all 4 stages
    load_stage(0, 0); CP_COMMIT();
    load_stage(1, 1); CP_COMMIT();
    load_stage(2, 2); CP_COMMIT();
    load_stage(3, 3); CP_COMMIT();

    // ldmatrix address precompute
    const int lane_r = lane & 15, chh = lane >> 4;
    uint32_t aoff[2]; uint32_t axr[2];
#pragma unroll
    for (int t = 0; t < 2; ++t) {
        int r = wm * 32 + t * 16 + lane_r;
        aoff[t] = (uint32_t)r * 64;
        axr[t]  = (uint32_t)((r >> 1) & 3);
    }
    const uint32_t xb = (uint32_t)(lane_r & 7);
    uint32_t bcol[4];
#pragma unroll
    for (int bb = 0; bb < 4; ++bb)
        bcol[bb] = (uint32_t)(wn * 8 + (((uint32_t)(bb * 2 + chh)) ^ xb)) * 16;
    const uint32_t boff[2] = {(uint32_t)lane_r * 256, (uint32_t)(16 + lane_r) * 256};

    float accG[2][8][4];
    float accM[2][8][4];
#pragma unroll
    for (int t = 0; t < 2; ++t)
#pragma unroll
        for (int nt = 0; nt < 8; ++nt)
#pragma unroll
            for (int i = 0; i < 4; ++i) { accG[t][nt][i] = 0.f; accM[t][nt][i] = 0.f; }

    for (int kt = 0; kt < 128; ++kt) {
        CP_WAIT3();          // group kt retired -> stage kt%4 is resident
        __syncthreads();

        const int st = kt & 3;
        const uint32_t Ahb = sb + SM_STAGES + st * STG_BYTES;
        const uint32_t Alb = Ahb + 8192;
        const uint32_t Bb  = Ahb + 16384;

#pragma unroll
        for (int ks = 0; ks < 2; ++ks) {
            uint32_t af[2][4], lf[2][4], bfr[4][4];
#pragma unroll
            for (int t = 0; t < 2; ++t) {
                uint32_t co = ((uint32_t)(ks * 2 + chh) ^ axr[t]) * 16;
                ldsm4(af[t], Ahb + aoff[t] + co);
                ldsm4(lf[t], Alb + aoff[t] + co);
            }
#pragma unroll
            for (int bb = 0; bb < 4; ++bb)
                ldsm4t(bfr[bb], Bb + boff[ks] + bcol[bb]);
#pragma unroll
            for (int t = 0; t < 2; ++t)
#pragma unroll
                for (int nt = 0; nt < 8; ++nt) {
                    const uint32_t* bp = &bfr[nt >> 1][(nt & 1) * 2];
                    mma_bf16(accG[t][nt], af[t], bp);
                    mma_bf16(accG[t][nt], lf[t], bp);
                }
        }

        if ((kt & 3) == 3) {   // end of 128-K group: fold with scales
            const int g = kt >> 2;
            const float* sg = s_sc + g * 128 + wn * 64 + (lane & 3) * 2;
#pragma unroll
            for (int nt = 0; nt < 8; ++nt) {
                float2 sv = *(const float2*)(sg + nt * 8);
#pragma unroll
                for (int t = 0; t < 2; ++t) {
                    accM[t][nt][0] += sv.x * accG[t][nt][0];
                    accM[t][nt][1] += sv.y * accG[t][nt][1];
                    accM[t][nt][2] += sv.x * accG[t][nt][2];
                    accM[t][nt][3] += sv.y * accG[t][nt][3];
                    accG[t][nt][0] = 0.f; accG[t][nt][1] = 0.f;
                    accG[t][nt][2] = 0.f; accG[t][nt][3] = 0.f;
                }
            }
        }

        __syncthreads();       // all warps done reading stage before refill
        if (kt + 4 < 128) load_stage(kt + 4, st);
        CP_COMMIT();           // always commit to keep group numbering uniform
    }

    // epilogue
#pragma unroll
    for (int t = 0; t < 2; ++t) {
        int row0 = m0 + wm * 32 + t * 16 + (lane >> 2);
#pragma unroll
        for (int nt = 0; nt < 8; ++nt) {
            int col = n0 + wn * 64 + nt * 8 + (lane & 3) * 2;
            float2 b = *(const float2*)(bias + col);
            float2 o0, o1;
            o0.x = accM[t][nt][0] + b.x;  o0.y = accM[t][nt][1] + b.y;
            o1.x = accM[t][nt][2] + b.x;  o1.y = accM[t][nt][3] + b.y;
            *(float2*)(C + (size_t)row0 * NNV + col)       = o0;
            *(float2*)(C + (size_t)(row0 + 8) * NNV + col) = o1;
        }
    }
}

// ---------------------------------------------------------------------------
// Host. Inputs: x, scales, zero_points, bias, qweight
// ---------------------------------------------------------------------------
extern "C" void kernel_launch(void* const* d_in, const int* in_sizes, int n_in,
                              void* d_out, int out_size)
{
    const float* x      = (const float*)d_in[0];
    const float* scales = (const float*)d_in[1];
    const float* zp     = (const float*)d_in[2];
    const float* bias   = (const float*)d_in[3];
    const int*   qw     = (const int*)d_in[4];
    float*       out    = (float*)d_out;

    split_x_kernel<<<(MMV * KKV / 4) / 256, 256>>>((const float4*)x);
    dequant_w_kernel<<<(KKV / 8) * NNV / 256, 256>>>(qw, zp);

    static bool attr_set = false;
    if (!attr_set) {
        cudaFuncSetAttribute(gemm_kernel, cudaFuncAttributeMaxDynamicSharedMemorySize, SMEM_TOTAL);
        attr_set = true;
    }
    gemm_kernel<<<dim3(NNV / 128, MMV / 128), 256, SMEM_TOTAL>>>(scales, bias, out);
}